// round 10
// baseline (speedup 1.0000x reference)
#include <cuda_runtime.h>
#include <cstdint>

// GIKDWConv: depthwise 7x7 conv, stride 1, pad 3, 4-fold-rotation-symmetrized
// weights. N=16, C=384, H=W=64, fp32.
//
// R10: work-stealing persistent version of R8. 740 blocks (148 SM x 5 CTAs)
// dynamically grab (n,cp) items off an atomic counter (reset each replay by
// a tiny first kernel in the graph). Per item the structure is EXACTLY R8's:
// two 32-row halves, 2 syncthreads total, cp.async slices interleaved into
// the FMA loops (half-1 during t=0 compute; NEXT item's half-0 during t=1
// compute, together with its weight symmetrization by 13 threads). Nothing
// serialized at item boundaries. Compute core unchanged: 8 rows x 2 cols per
// thread, channel pairs packed in f32x2 (fma.rn.f32x2), 13 unique weights.

#define HH 64
#define WW 64
#define NN 16
#define CC 384
#define TR 38              // tile rows: 32 output + 6 halo
#define TC 70              // tile cols: 64 output + 6 halo
#define CELLS (TR * TC)    // 2660
#define NSLICE 21          // ceil(2660/128)
#define RPT 8              // output rows per thread
#define NITEMS 3072        // (n, channel-pair) items
#define NBLK 740           // 148 SMs x 5 CTAs
typedef unsigned long long ull;

// orbit id of each (ky,kx) tap under 90-degree rotation (13 unique weights)
__device__ constexpr int ORBIT[7][7] = {
    {0, 1, 2, 3, 4, 5, 0},
    {5, 6, 7, 8, 9, 6, 1},
    {4, 9,10,11,10, 7, 2},
    {3, 8,11,12,11, 8, 3},
    {2, 7,10,11,10, 9, 4},
    {1, 6, 9, 8, 7, 6, 5},
    {0, 5, 4, 3, 2, 1, 0}};
__device__ constexpr int REP_I[13] = {0,0,0,0,0,0,1,1,1,1,2,2,3};
__device__ constexpr int REP_J[13] = {0,1,2,3,4,5,1,2,3,4,2,3,3};

__device__ unsigned int g_ctr;

__device__ __forceinline__ ull fma2(ull a, ull b, ull c) {
    ull d;
    asm("fma.rn.f32x2 %0, %1, %2, %3;" : "=l"(d) : "l"(a), "l"(b), "l"(c));
    return d;
}
__device__ __forceinline__ ull pack2(float lo, float hi) {
    ull r;
    asm("mov.b64 %0, {%1, %2};" : "=l"(r) : "f"(lo), "f"(hi));
    return r;
}
__device__ __forceinline__ void unpack2(ull v, float& lo, float& hi) {
    asm("mov.b64 {%0, %1}, %2;" : "=f"(lo), "=f"(hi) : "l"(v));
}
__device__ __forceinline__ uint32_t s2u(const void* p) {
    uint32_t a;
    asm("{ .reg .u64 t; cvta.to.shared.u64 t, %1; cvt.u32.u64 %0, t; }"
        : "=r"(a) : "l"(p));
    return a;
}
// 4-byte cp.async with zfill: sz=4 copies, sz=0 writes zeros (no src access)
__device__ __forceinline__ void cp4(uint32_t d, const float* s, int sz) {
    asm volatile("cp.async.ca.shared.global [%0], [%1], 4, %2;"
                 :: "r"(d), "l"(s), "r"(sz));
}

__global__ void reset_kernel() { g_ctr = 0u; }

__global__ __launch_bounds__(128, 5)
void gik_dwconv_kernel(const float* __restrict__ x,
                       const float* __restrict__ weight,
                       float* __restrict__ out) {
    __shared__ ull sx[2 * CELLS];      // buf0 = half-0, buf1 = half-1
    __shared__ ull sw[2][13];          // weights, ping-pong by item parity
    __shared__ unsigned int s_nid;     // next stolen item id

    const int tid = threadIdx.x;
    const uint32_t sbase = s2u(sx);

    // one 128-cell cp.async slice (gy0 = first global row of the half-tile)
    auto slice = [&](int s, const float* x0, const float* x1,
                     uint32_t dst0, int gy0) {
        int cell = s * 128 + tid;
        if (cell < CELLS) {
            int r  = cell / TC;
            int c  = cell - r * TC;
            int gy = gy0 + r, gx = c - 3;
            int v  = ((unsigned)gy < (unsigned)HH) &
                     ((unsigned)gx < (unsigned)WW);
            int off = v ? (gy * WW + gx) : 0;
            int sz  = v ? 4 : 0;
            cp4(dst0 + cell * 8,     x0 + off, sz);
            cp4(dst0 + cell * 8 + 4, x1 + off, sz);
        }
    };
    // symmetrize the 13 unique weights for channel pair cp into sw[slot]
    auto symw = [&](int cp, int slot) {
        const int i = REP_I[tid], j = REP_J[tid];
        const float* w0 = weight + cp * 98;
        const float* w1 = w0 + 49;
        float a0 = 0.25f * (w0[i*7 + j] + w0[j*7 + (6-i)] +
                            w0[(6-i)*7 + (6-j)] + w0[(6-j)*7 + i]);
        float a1 = 0.25f * (w1[i*7 + j] + w1[j*7 + (6-i)] +
                            w1[(6-i)*7 + (6-j)] + w1[(6-j)*7 + i]);
        sw[slot][tid] = pack2(a0, a1);
    };

    // ---- steal first item; prologue-load its half-0 + weights ----
    int id = blockIdx.x;               // deterministic first assignment
    int n  = id / 192;
    int cp = id - n * 192;
    const float* x0 = x + ((n * CC + cp * 2) * (HH * WW));
    const float* x1 = x0 + HH * WW;
    #pragma unroll
    for (int s = 0; s < NSLICE; s++) slice(s, x0, x1, sbase, -3);
    asm volatile("cp.async.commit_group;" ::: "memory");
    if (tid == 0) s_nid = atomicAdd(&g_ctr, 1u) + NBLK;  // skip first wave
    if (tid < 13) symw(cp, 0);

    const int cx = (tid & 31) * 2;     // even output column 0..62
    const int r0 = (tid >> 5) * RPT;   // local output row base: 0,8,16,24

    asm volatile("cp.async.wait_group 0;" ::: "memory");
    __syncthreads();                   // half-0 + sw[0] + s_nid ready

    int p = 0;
    for (;;) {
        ull wreg[13];
        #pragma unroll
        for (int o = 0; o < 13; o++) wreg[o] = sw[p][o];

        float* o0 = out + ((n * CC + cp * 2) * (HH * WW));
        float* o1 = o0 + HH * WW;

        // ======== t = 0: compute half-0, interleave half-1 load ========
        {
            ull acc0[RPT], acc1[RPT];
            #pragma unroll
            for (int r = 0; r < RPT; r++) { acc0[r] = 0ull; acc1[r] = 0ull; }
            #pragma unroll
            for (int y = 0; y < RPT + 6; y++) {
                ull xv[8];
                {
                    const ulonglong2* rp =
                        (const ulonglong2*)(sx + (r0 + y) * TC + cx);
                    #pragma unroll
                    for (int q = 0; q < 4; q++) {
                        ulonglong2 v = rp[q];
                        xv[2*q] = v.x; xv[2*q+1] = v.y;
                    }
                }
                slice(y, x0, x1, sbase + CELLS * 8, 29);
                if (y < NSLICE - 14)
                    slice(y + 14, x0, x1, sbase + CELLS * 8, 29);
                #pragma unroll
                for (int k = 0; k < 7; k++) {
                    const int r = y - k;
                    if (r >= 0 && r < RPT) {
                        #pragma unroll
                        for (int u = 0; u < 7; u++) {
                            const ull w = wreg[ORBIT[k][u]];
                            acc0[r] = fma2(w, xv[u],     acc0[r]);
                            acc1[r] = fma2(w, xv[u + 1], acc1[r]);
                        }
                    }
                }
            }
            asm volatile("cp.async.commit_group;" ::: "memory");
            #pragma unroll
            for (int r = 0; r < RPT; r++) {
                float a, b, c, d;
                unpack2(acc0[r], a, b);
                unpack2(acc1[r], c, d);
                const int off = (r0 + r) * WW + cx;
                *(float2*)(o0 + off) = make_float2(a, c);
                *(float2*)(o1 + off) = make_float2(b, d);
            }
        }
        asm volatile("cp.async.wait_group 0;" ::: "memory");
        __syncthreads();               // half-1 ready; buf0 free; s_nid set

        const int nid = (int)s_nid;
        const bool hn = nid < NITEMS;
        int n2 = 0, cp2 = 0;
        const float *nx0 = x, *nx1 = x;
        if (hn) {
            n2  = nid / 192;
            cp2 = nid - n2 * 192;
            nx0 = x + ((n2 * CC + cp2 * 2) * (HH * WW));
            nx1 = nx0 + HH * WW;
        }

        // == t = 1: compute half-1, interleave NEXT item's half-0 load ==
        {
            if (tid == 0 && hn) s_nid = atomicAdd(&g_ctr, 1u) + NBLK;
            if (tid < 13 && hn) symw(cp2, p ^ 1);
            ull acc0[RPT], acc1[RPT];
            #pragma unroll
            for (int r = 0; r < RPT; r++) { acc0[r] = 0ull; acc1[r] = 0ull; }
            const ull* sb = sx + CELLS;
            #pragma unroll
            for (int y = 0; y < RPT + 6; y++) {
                ull xv[8];
                {
                    const ulonglong2* rp =
                        (const ulonglong2*)(sb + (r0 + y) * TC + cx);
                    #pragma unroll
                    for (int q = 0; q < 4; q++) {
                        ulonglong2 v = rp[q];
                        xv[2*q] = v.x; xv[2*q+1] = v.y;
                    }
                }
                if (hn) {
                    slice(y, nx0, nx1, sbase, -3);
                    if (y < NSLICE - 14) slice(y + 14, nx0, nx1, sbase, -3);
                }
                #pragma unroll
                for (int k = 0; k < 7; k++) {
                    const int r = y - k;
                    if (r >= 0 && r < RPT) {
                        #pragma unroll
                        for (int u = 0; u < 7; u++) {
                            const ull w = wreg[ORBIT[k][u]];
                            acc0[r] = fma2(w, xv[u],     acc0[r]);
                            acc1[r] = fma2(w, xv[u + 1], acc1[r]);
                        }
                    }
                }
            }
            if (hn)
                asm volatile("cp.async.commit_group;" ::: "memory");
            o0 += 32 * WW; o1 += 32 * WW;
            #pragma unroll
            for (int r = 0; r < RPT; r++) {
                float a, b, c, d;
                unpack2(acc0[r], a, b);
                unpack2(acc1[r], c, d);
                const int off = (r0 + r) * WW + cx;
                *(float2*)(o0 + off) = make_float2(a, c);
                *(float2*)(o1 + off) = make_float2(b, d);
            }
        }
        if (!hn) break;
        asm volatile("cp.async.wait_group 0;" ::: "memory");
        __syncthreads();               // next half-0 + sw[p^1] + s_nid ready

        id = nid; n = n2; cp = cp2; x0 = nx0; x1 = nx1; p ^= 1;
    }
}

extern "C" void kernel_launch(void* const* d_in, const int* in_sizes, int n_in,
                              void* d_out, int out_size) {
    const float* x = (const float*)d_in[0];       // [16,384,64,64]
    const float* w = (const float*)d_in[1];       // [384,1,7,7]
    float* out = (float*)d_out;                   // [16,384,64,64]
    reset_kernel<<<1, 1>>>();
    gik_dwconv_kernel<<<NBLK, 128>>>(x, w, out);
}

// round 11
// speedup vs baseline: 1.2008x; 1.2008x over previous
#include <cuda_runtime.h>
#include <cstdint>

// GIKDWConv: depthwise 7x7 conv, stride 1, pad 3, 4-fold-rotation-symmetrized
// weights. N=16, C=384, H=W=64, fp32.
//
// R11: R8's structure at finer grain to kill the wave-tail (3072 blocks /
// 740 resident slots = 4 waves + sparse 5th = 83% tail efficiency; 6144
// blocks -> 8.3/slot = 92%). Each block = one (n, channel-pair, 32-row half)
// processed as two 16-row quarters: burst-load q0, compute q0 with q1's
// cp.async slices interleaved into the FMA stream, compute q1. Core
// unchanged: 4 rows x 2 cols per thread, channel pairs packed in f32x2
// (fma.rn.f32x2), 13 unique symmetrized weights in registers, 5 CTAs/SM.

#define HH 64
#define WW 64
#define NN 16
#define CC 384
#define TR 22              // tile rows: 16 output + 6 halo
#define TC 70              // tile cols: 64 output + 6 halo
#define CELLS (TR * TC)    // 1540
#define NSLICE 13          // ceil(1540/128)
#define RPT 4              // output rows per thread
typedef unsigned long long ull;

// orbit id of each (ky,kx) tap under 90-degree rotation (13 unique weights)
__device__ constexpr int ORBIT[7][7] = {
    {0, 1, 2, 3, 4, 5, 0},
    {5, 6, 7, 8, 9, 6, 1},
    {4, 9,10,11,10, 7, 2},
    {3, 8,11,12,11, 8, 3},
    {2, 7,10,11,10, 9, 4},
    {1, 6, 9, 8, 7, 6, 5},
    {0, 5, 4, 3, 2, 1, 0}};
__device__ constexpr int REP_I[13] = {0,0,0,0,0,0,1,1,1,1,2,2,3};
__device__ constexpr int REP_J[13] = {0,1,2,3,4,5,1,2,3,4,2,3,3};

__device__ __forceinline__ ull fma2(ull a, ull b, ull c) {
    ull d;
    asm("fma.rn.f32x2 %0, %1, %2, %3;" : "=l"(d) : "l"(a), "l"(b), "l"(c));
    return d;
}
__device__ __forceinline__ ull pack2(float lo, float hi) {
    ull r;
    asm("mov.b64 %0, {%1, %2};" : "=l"(r) : "f"(lo), "f"(hi));
    return r;
}
__device__ __forceinline__ void unpack2(ull v, float& lo, float& hi) {
    asm("mov.b64 {%0, %1}, %2;" : "=f"(lo), "=f"(hi) : "l"(v));
}
__device__ __forceinline__ uint32_t s2u(const void* p) {
    uint32_t a;
    asm("{ .reg .u64 t; cvta.to.shared.u64 t, %1; cvt.u32.u64 %0, t; }"
        : "=r"(a) : "l"(p));
    return a;
}
// 4-byte cp.async with zfill: sz=4 copies, sz=0 writes zeros (no src access)
__device__ __forceinline__ void cp4(uint32_t d, const float* s, int sz) {
    asm volatile("cp.async.ca.shared.global [%0], [%1], 4, %2;"
                 :: "r"(d), "l"(s), "r"(sz));
}

__global__ __launch_bounds__(128, 5)
void gik_dwconv_kernel(const float* __restrict__ x,
                       const float* __restrict__ weight,
                       float* __restrict__ out) {
    __shared__ ull sx[2 * CELLS];   // double-buffered packed quarter-tiles
    __shared__ ull sw[13];          // packed symmetric weights

    const int tid  = threadIdx.x;
    const int cp   = blockIdx.x;        // channel pair 0..191
    const int n    = blockIdx.y;        // batch 0..15
    const int half = blockIdx.z;        // vertical half 0..1
    const int c0   = cp * 2;

    const float* x0 = x + ((n * CC + c0) * (HH * WW));
    const float* x1 = x0 + HH * WW;
    const uint32_t sbase = s2u(sx);

    // one 128-cell slice of a quarter-tile load (interleaved-packed cp.async)
    auto slice = [&](int s, uint32_t dst0, int gy0) {
        int cell = s * 128 + tid;
        if (cell < CELLS) {
            int r  = cell / TC;
            int c  = cell - r * TC;
            int gy = gy0 + r, gx = c - 3;
            int v  = ((unsigned)gy < (unsigned)HH) &
                     ((unsigned)gx < (unsigned)WW);
            int off = v ? (gy * WW + gx) : 0;
            int sz  = v ? 4 : 0;
            cp4(dst0 + cell * 8,     x0 + off, sz);
            cp4(dst0 + cell * 8 + 4, x1 + off, sz);
        }
    };

    // ---- prologue: load quarter 0 (rows half*32-3 ..) into buffer 0 ----
    const int gyq0 = half * 32 - 3;
    #pragma unroll
    for (int s = 0; s < NSLICE; s++) slice(s, sbase, gyq0);
    asm volatile("cp.async.commit_group;" ::: "memory");

    // ---- the 13 unique symmetrized weights (LDG overlaps the cp.async) ----
    if (tid < 13) {
        const int i = REP_I[tid], j = REP_J[tid];
        const float* w0 = weight + c0 * 49;
        const float* w1 = w0 + 49;
        float a0 = 0.25f * (w0[i*7 + j] + w0[j*7 + (6-i)] +
                            w0[(6-i)*7 + (6-j)] + w0[(6-j)*7 + i]);
        float a1 = 0.25f * (w1[i*7 + j] + w1[j*7 + (6-i)] +
                            w1[(6-i)*7 + (6-j)] + w1[(6-j)*7 + i]);
        sw[tid] = pack2(a0, a1);
    }

    const int cx = (tid & 31) * 2;     // even output column 0..62
    const int r0 = (tid >> 5) * RPT;   // local output row base: 0,4,8,12

    asm volatile("cp.async.wait_group 0;" ::: "memory");
    __syncthreads();                   // quarter 0 + weights visible

    ull wreg[13];
    #pragma unroll
    for (int o = 0; o < 13; o++) wreg[o] = sw[o];

    #pragma unroll
    for (int t = 0; t < 2; t++) {
        const ull* sb = sx + t * CELLS;

        ull acc0[RPT], acc1[RPT];      // col cx and cx+1
        #pragma unroll
        for (int r = 0; r < RPT; r++) { acc0[r] = 0ull; acc1[r] = 0ull; }

        #pragma unroll
        for (int y = 0; y < RPT + 6; y++) {
            ull xv[8];                 // 8 packed inputs: 4x LDS.128
            {
                const ulonglong2* rp =
                    (const ulonglong2*)(sb + (r0 + y) * TC + cx);
                #pragma unroll
                for (int q = 0; q < 4; q++) {
                    ulonglong2 v = rp[q];
                    xv[2*q] = v.x; xv[2*q+1] = v.y;
                }
            }
            // interleaved prefetch of quarter 1 into buffer 1 (t=0 only):
            // slices y (all 10 iters) and y+10 (first 3) -> 13 slices
            if (t == 0) {
                slice(y, sbase + CELLS * 8, gyq0 + 16);
                if (y < NSLICE - 10) slice(y + 10, sbase + CELLS * 8, gyq0 + 16);
            }
            #pragma unroll
            for (int k = 0; k < 7; k++) {
                const int r = y - k;
                if (r >= 0 && r < RPT) {
                    #pragma unroll
                    for (int u = 0; u < 7; u++) {
                        const ull w = wreg[ORBIT[k][u]];
                        acc0[r] = fma2(w, xv[u],     acc0[r]);
                        acc1[r] = fma2(w, xv[u + 1], acc1[r]);
                    }
                }
            }
        }
        if (t == 0)
            asm volatile("cp.async.commit_group;" ::: "memory");

        // ---- store: float2 per channel-row ----
        float* o0 = out + ((n * CC + c0) * (HH * WW))
                        + (half * 32 + t * 16) * WW;
        float* o1 = o0 + HH * WW;
        #pragma unroll
        for (int r = 0; r < RPT; r++) {
            float a, b, c, d;
            unpack2(acc0[r], a, b);     // a: c0 col cx,   b: c1 col cx
            unpack2(acc1[r], c, d);     // c: c0 col cx+1, d: c1 col cx+1
            const int off = (r0 + r) * WW + cx;
            *(float2*)(o0 + off) = make_float2(a, c);
            *(float2*)(o1 + off) = make_float2(b, d);
        }
        if (t == 0) {
            asm volatile("cp.async.wait_group 0;" ::: "memory");
            __syncthreads();           // quarter 1 fully resident in buffer 1
        }
    }
}

extern "C" void kernel_launch(void* const* d_in, const int* in_sizes, int n_in,
                              void* d_out, int out_size) {
    const float* x = (const float*)d_in[0];       // [16,384,64,64]
    const float* w = (const float*)d_in[1];       // [384,1,7,7]
    float* out = (float*)d_out;                   // [16,384,64,64]
    dim3 grid(CC / 2, NN, 2);
    gik_dwconv_kernel<<<grid, 128>>>(x, w, out);
}

// round 12
// speedup vs baseline: 1.3746x; 1.1447x over previous
#include <cuda_runtime.h>
#include <cstdint>

// GIKDWConv: depthwise 7x7 conv, stride 1, pad 3, 4-fold-rotation-symmetrized
// weights. N=16, C=384, H=W=64, fp32.
//
// R12: R8 structure + FLOP cut via C4 pair-sum factoring. The symmetrized
// filter's rows k / 6-k share matched coefficient pairs and row 3 is a
// palindrome, so per input row the sums u06=x0+x6, u15=x1+x5, u24=x2+x4
// are shared across k in {0,6,3}, {1,5,3}, {2,4,3}. Row work drops from
// 98 FFMA2 (rt3 each: 3 distinct 64b operands hit the RF bank limit) to
// 80 FFMA2 + 6 FADD2 (rt2) per 2-col iteration: -14% RF cycles. Prefetch
// slices front-loaded (3/iter for y<7) so the half-boundary wait_group
// exposes no DRAM latency. Everything else identical to R8.

#define HH 64
#define WW 64
#define NN 16
#define CC 384
#define TR 38              // tile rows: 32 output + 6 halo
#define TC 70              // tile cols: 64 output + 6 halo
#define CELLS (TR * TC)    // 2660
#define NSLICE 21          // ceil(2660/128)
#define RPT 8              // output rows per thread
typedef unsigned long long ull;

__device__ constexpr int REP_I[13] = {0,0,0,0,0,0,1,1,1,1,2,2,3};
__device__ constexpr int REP_J[13] = {0,1,2,3,4,5,1,2,3,4,2,3,3};

// factored row formulas: per k, up to 6 (coef, src) terms.
// src indexes: 0=u06, 1..5 = x1..x5, 6=x0, 7=x6, 8=u15, 9=u24
// (for column B every x index shifts by +1; u's use the B variants)
__device__ constexpr int KNT[7]      = {6,6,6,4,6,6,6};
__device__ constexpr int KC[7][6] = {
    {0, 1, 2, 3, 4, 5},        // k=0: a0*u06 + a1x1+a2x2+a3x3+a4x4+a5x5
    {6, 5, 7, 8, 9, 1},        // k=1: a6*u15 + a5x0+a7x2+a8x3+a9x4+a1x6
    {10,4, 9, 11,7, 2},        // k=2: a10*u24 + a4x0+a9x1+a11x3+a7x5+a2x6
    {3, 8, 11,12,0, 0},        // k=3: a3*u06+a8*u15+a11*u24+a12x3
    {10,2, 7, 11,9, 4},        // k=4: a10*u24 + a2x0+a7x1+a11x3+a9x5+a4x6
    {6, 1, 9, 8, 7, 5},        // k=5: a6*u15 + a1x0+a9x2+a8x3+a7x4+a5x6
    {0, 5, 4, 3, 2, 1}};       // k=6: a0*u06 + a5x1+a4x2+a3x3+a2x4+a1x5
__device__ constexpr int KS[7][6] = {
    {0, 1, 2, 3, 4, 5},
    {8, 6, 2, 3, 4, 7},
    {9, 6, 1, 3, 5, 7},
    {0, 8, 9, 3, 0, 0},
    {9, 6, 1, 3, 5, 7},
    {8, 6, 2, 3, 4, 7},
    {0, 1, 2, 3, 4, 5}};

__device__ __forceinline__ ull fma2(ull a, ull b, ull c) {
    ull d;
    asm("fma.rn.f32x2 %0, %1, %2, %3;" : "=l"(d) : "l"(a), "l"(b), "l"(c));
    return d;
}
__device__ __forceinline__ ull add2(ull a, ull b) {
    ull d;
    asm("add.rn.f32x2 %0, %1, %2;" : "=l"(d) : "l"(a), "l"(b));
    return d;
}
__device__ __forceinline__ ull pack2(float lo, float hi) {
    ull r;
    asm("mov.b64 %0, {%1, %2};" : "=l"(r) : "f"(lo), "f"(hi));
    return r;
}
__device__ __forceinline__ void unpack2(ull v, float& lo, float& hi) {
    asm("mov.b64 {%0, %1}, %2;" : "=f"(lo), "=f"(hi) : "l"(v));
}
__device__ __forceinline__ uint32_t s2u(const void* p) {
    uint32_t a;
    asm("{ .reg .u64 t; cvta.to.shared.u64 t, %1; cvt.u32.u64 %0, t; }"
        : "=r"(a) : "l"(p));
    return a;
}
// 4-byte cp.async with zfill: sz=4 copies, sz=0 writes zeros (no src access)
__device__ __forceinline__ void cp4(uint32_t d, const float* s, int sz) {
    asm volatile("cp.async.ca.shared.global [%0], [%1], 4, %2;"
                 :: "r"(d), "l"(s), "r"(sz));
}

__global__ __launch_bounds__(128, 5)
void gik_dwconv_kernel(const float* __restrict__ x,
                       const float* __restrict__ weight,
                       float* __restrict__ out) {
    __shared__ ull sx[2 * CELLS];   // double-buffered packed half-tiles
    __shared__ ull sw[13];          // packed symmetric weights

    const int tid = threadIdx.x;
    const int cp  = blockIdx.x;         // channel pair 0..191
    const int n   = blockIdx.y;         // batch 0..15
    const int c0  = cp * 2;

    const float* x0 = x + ((n * CC + c0) * (HH * WW));
    const float* x1 = x0 + HH * WW;
    const uint32_t sbase = s2u(sx);

    // one 128-cell slice of a half-tile load (interleaved-packed cp.async)
    auto slice = [&](int s, uint32_t dst0, int gy0) {
        int cell = s * 128 + tid;
        if (cell < CELLS) {
            int r  = cell / TC;
            int c  = cell - r * TC;
            int gy = gy0 + r, gx = c - 3;
            int v  = ((unsigned)gy < (unsigned)HH) &
                     ((unsigned)gx < (unsigned)WW);
            int off = v ? (gy * WW + gx) : 0;
            int sz  = v ? 4 : 0;
            cp4(dst0 + cell * 8,     x0 + off, sz);
            cp4(dst0 + cell * 8 + 4, x1 + off, sz);
        }
    };

    // ---- prologue: load half 0 into buffer 0 ----
    #pragma unroll
    for (int s = 0; s < NSLICE; s++) slice(s, sbase, -3);
    asm volatile("cp.async.commit_group;" ::: "memory");

    // ---- the 13 unique symmetrized weights (LDG overlaps the cp.async) ----
    if (tid < 13) {
        const int i = REP_I[tid], j = REP_J[tid];
        const float* w0 = weight + c0 * 49;
        const float* w1 = w0 + 49;
        float a0 = 0.25f * (w0[i*7 + j] + w0[j*7 + (6-i)] +
                            w0[(6-i)*7 + (6-j)] + w0[(6-j)*7 + i]);
        float a1 = 0.25f * (w1[i*7 + j] + w1[j*7 + (6-i)] +
                            w1[(6-i)*7 + (6-j)] + w1[(6-j)*7 + i]);
        sw[tid] = pack2(a0, a1);
    }

    const int cx = (tid & 31) * 2;     // even output column 0..62
    const int r0 = (tid >> 5) * RPT;   // local output row base: 0,8,16,24

    asm volatile("cp.async.wait_group 0;" ::: "memory");
    __syncthreads();                   // half 0 + weights visible

    ull wreg[13];
    #pragma unroll
    for (int o = 0; o < 13; o++) wreg[o] = sw[o];

    #pragma unroll
    for (int t = 0; t < 2; t++) {
        const ull* sb = sx + t * CELLS;

        ull acc0[RPT], acc1[RPT];      // col cx and cx+1
        #pragma unroll
        for (int r = 0; r < RPT; r++) { acc0[r] = 0ull; acc1[r] = 0ull; }

        #pragma unroll
        for (int y = 0; y < RPT + 6; y++) {
            ull xv[8];                 // 8 packed inputs: 4x LDS.128
            {
                const ulonglong2* rp =
                    (const ulonglong2*)(sb + (r0 + y) * TC + cx);
                #pragma unroll
                for (int q = 0; q < 4; q++) {
                    ulonglong2 v = rp[q];
                    xv[2*q] = v.x; xv[2*q+1] = v.y;
                }
            }
            // front-loaded prefetch of half 1 (t=0): 3 slices/iter, y<7
            if (t == 0 && y < 7) {
                slice(3*y,     sbase + CELLS * 8, 29);
                slice(3*y + 1, sbase + CELLS * 8, 29);
                slice(3*y + 2, sbase + CELLS * 8, 29);
                if (y == 6)
                    asm volatile("cp.async.commit_group;" ::: "memory");
            }
            // shared pair-sums (FADD2, rt2) for cols A (cx) and B (cx+1)
            ull sA[10], sB[10];
            sA[0] = add2(xv[0], xv[6]);  sB[0] = add2(xv[1], xv[7]);  // u06
            sA[8] = add2(xv[1], xv[5]);  sB[8] = add2(xv[2], xv[6]);  // u15
            sA[9] = add2(xv[2], xv[4]);  sB[9] = add2(xv[3], xv[5]);  // u24
            sA[1]=xv[1]; sA[2]=xv[2]; sA[3]=xv[3]; sA[4]=xv[4];
            sA[5]=xv[5]; sA[6]=xv[0]; sA[7]=xv[6];
            sB[1]=xv[2]; sB[2]=xv[3]; sB[3]=xv[4]; sB[4]=xv[5];
            sB[5]=xv[6]; sB[6]=xv[1]; sB[7]=xv[7];

            #pragma unroll
            for (int k = 0; k < 7; k++) {
                const int r = y - k;
                if (r >= 0 && r < RPT) {
                    #pragma unroll
                    for (int u = 0; u < 6; u++) {
                        if (u < KNT[k]) {
                            const ull w = wreg[KC[k][u]];
                            acc0[r] = fma2(w, sA[KS[k][u]], acc0[r]);
                            acc1[r] = fma2(w, sB[KS[k][u]], acc1[r]);
                        }
                    }
                }
            }
        }

        // ---- store: float2 per channel-row ----
        float* o0 = out + ((n * CC + c0) * (HH * WW)) + t * 32 * WW;
        float* o1 = o0 + HH * WW;
        #pragma unroll
        for (int r = 0; r < RPT; r++) {
            float a, b, c, d;
            unpack2(acc0[r], a, b);     // a: c0 col cx,   b: c1 col cx
            unpack2(acc1[r], c, d);     // c: c0 col cx+1, d: c1 col cx+1
            const int off = (r0 + r) * WW + cx;
            *(float2*)(o0 + off) = make_float2(a, c);
            *(float2*)(o1 + off) = make_float2(b, d);
        }
        if (t == 0) {
            asm volatile("cp.async.wait_group 0;" ::: "memory");
            __syncthreads();           // half 1 fully resident in buffer 1
        }
    }
}

extern "C" void kernel_launch(void* const* d_in, const int* in_sizes, int n_in,
                              void* d_out, int out_size) {
    const float* x = (const float*)d_in[0];       // [16,384,64,64]
    const float* w = (const float*)d_in[1];       // [384,1,7,7]
    float* out = (float*)d_out;                   // [16,384,64,64]
    dim3 grid(CC / 2, NN);
    gik_dwconv_kernel<<<grid, 128>>>(x, w, out);
}